// round 14
// baseline (speedup 1.0000x reference)
#include <cuda_runtime.h>

#define BB 16
#define NL 200
#define LL 64
#define CF 64
#define HW 256
#define NB 32

// Output layout (float32, flattened in reference-return order)
#define OFF_NORM  0         // (B,N,2)
#define OFF_CIMG  6400      // (B,N,2)
#define OFF_CBODY 12800     // (B,N,3)
#define OFF_PF    22400     // (B,N,64)
#define OFF_PB    227200    // (B,N,64)
#define OFF_VALID 432000    // (B,N)
#define OFF_AMP   435200    // (B,N)
#define OFF_SLOPE 438400    // (B,N)
#define OFF_FEAT  441600    // (B,C,N,64)

struct LineParams {
    float cix, ciy, nix, niy;
    float c0, c1, c2;
    bool  vline;
};

// dot3 with explicit left-to-right rounded adds, no FMA (matches XLA reduce order)
__device__ __forceinline__ float dot3(float a0, float a1, float a2,
                                      float b0, float b1, float b2) {
    return __fadd_rn(__fadd_rn(__fmul_rn(a0, b0), __fmul_rn(a1, b1)),
                     __fmul_rn(a2, b2));
}

__device__ __forceinline__ LineParams compute_line(
    const float* __restrict__ pose,
    const float* __restrict__ cam,
    const float* __restrict__ tv,
    int b, int n)
{
    const float* P = pose + b * 12;
    const float* C = cam + b * 6;
    const float* T = tv + (b * NL + n) * 8;
    float c0 = T[0], c1 = T[1], c2 = T[2];
    float n0 = T[3], n1 = T[4], n2 = T[5];
    float fg = T[6], bg = T[7];

    float civx = __fadd_rn(dot3(c0, c1, c2, P[0], P[1], P[2]), P[9]);
    float civy = __fadd_rn(dot3(c0, c1, c2, P[3], P[4], P[5]), P[10]);
    float civz = __fadd_rn(dot3(c0, c1, c2, P[6], P[7], P[8]), P[11]);
    float nvx  = dot3(n0, n1, n2, P[0], P[1], P[2]);
    float nvy  = dot3(n0, n1, n2, P[3], P[4], P[5]);

    float sw = C[0], sh = C[1], fx = C[2], fy = C[3], cx = C[4], cy = C[5];
    float zz = fmaxf(civz, 1e-4f);
    float cix = __fadd_rn(__fmul_rn(__fdiv_rn(civx, zz), fx), cx);
    float ciy = __fadd_rn(__fmul_rn(__fdiv_rn(civy, zz), fy), cy);

    bool cvalid = (civz > 1e-4f) &&
                  (cix >= 0.f) && (cix <= __fsub_rn(sw, 1.f)) &&
                  (ciy >= 0.f) && (ciy <= __fsub_rn(sh, 1.f));

    float nn  = __fsqrt_rn(__fadd_rn(__fmul_rn(nvx, nvx), __fmul_rn(nvy, nvy)));
    float nd  = fmaxf(nn, 1e-12f);
    float nix = __fdiv_rn(nvx, nd);
    float niy = __fdiv_rn(nvy, nd);

    float cfg = __fdiv_rn(__fmul_rn(fg, fx), civz);
    float cbg = __fdiv_rn(__fmul_rn(bg, fx), civz);
    bool vline = (fminf(cfg, cbg) >= 6.0f) && cvalid;

    float p0x = __fadd_rn(cix, __fmul_rn(-31.5f, nix));
    float p0y = __fadd_rn(ciy, __fmul_rn(-31.5f, niy));
    float p1x = __fadd_rn(cix, __fmul_rn( 31.5f, nix));
    float p1y = __fadd_rn(ciy, __fmul_rn( 31.5f, niy));
    vline = vline &&
        (p0x >= 0.f) && (p0x < (float)HW) && (p0y >= 0.f) && (p0y < (float)HW) &&
        (p1x >= 0.f) && (p1x < (float)HW) && (p1y >= 0.f) && (p1y < (float)HW);

    LineParams lp;
    lp.cix = cix; lp.ciy = ciy; lp.nix = nix; lp.niy = niy;
    lp.c0 = c0; lp.c1 = c1; lp.c2 = c2;
    lp.vline = vline;
    return lp;
}

// Reference grid chain, bit-exact:
//   g = p/size*2 - 1 ;  x = ((g + 1)*size - 1)*0.5
__device__ __forceinline__ float grid_unnorm(float p) {
    float t = __fdiv_rn(p, (float)HW);
    float g = __fsub_rn(__fmul_rn(t, 2.f), 1.f);
    return __fmul_rn(__fsub_rn(__fmul_rn(__fadd_rn(g, 1.f), (float)HW), 1.f), 0.5f);
}

// Per-(point,row) gather descriptor: 4-wide quad weights + cross fixup.
struct GDesc {
    float W0, W1, W2, W3, ew;
    int   qoff, eoff;
};

__device__ __forceinline__ GDesc make_desc(const LineParams& lp, int pt, int r)
{
    float s = __fsub_rn((float)pt, 31.5f);
    float x = grid_unnorm(__fadd_rn(lp.cix, __fmul_rn(s, lp.nix)));
    float y = grid_unnorm(__fadd_rn(lp.ciy, __fmul_rn(s, lp.niy)));

    float x0f = floorf(x), y0f = floorf(y);
    float wx1 = __fsub_rn(x, x0f), wy1 = __fsub_rn(y, y0f);
    float wx0 = __fsub_rn(1.f, wx1), wy0 = __fsub_rn(1.f, wy1);
    int x0 = (int)x0f, y0 = (int)y0f;
    int x1 = x0 + 1, y1 = y0 + 1;

    bool vx0 = (x0 >= 0) && (x0 < HW), vx1 = (x1 >= 0) && (x1 < HW);
    bool vy0 = (y0 >= 0) && (y0 < HW), vy1 = (y1 >= 0) && (y1 < HW);
    int xc0 = min(max(x0, 0), HW - 1), xc1 = min(max(x1, 0), HW - 1);
    int yc0 = min(max(y0, 0), HW - 1), yc1 = min(max(y1, 0), HW - 1);

    // this lane's row weights: r==0 -> (w00, w10), r==1 -> (w01, w11)
    float wyr = r ? wy1 : wy0;
    bool  vyr = r ? vy1 : vy0;
    float wl  = (vx0 && vyr) ? __fmul_rn(wx0, wyr) : 0.f;
    float wrt = (vx1 && vyr) ? __fmul_rn(wx1, wyr) : 0.f;
    int   yrr = r ? yc1 : yc0;

    int qx = xc0 & ~3;
    int i0 = xc0 - qx;             // 0..3
    int i1 = i0 + (xc1 - xc0);     // 0..4
    bool cross = (i1 > 3);

    float W[4];
    #pragma unroll
    for (int k = 0; k < 4; k++) {
        float a = (k == i0) ? wl : 0.f;
        if (!cross && k == i1) a += wrt;
        W[k] = a;
    }
    GDesc d;
    d.W0 = W[0]; d.W1 = W[1]; d.W2 = W[2]; d.W3 = W[3];
    d.ew = cross ? wrt : 0.f;
    d.qoff = yrr * HW + qx;
    d.eoff = yrr * HW + xc1;
    return d;
}

// Fused kernel. grid (NL, BB), block 256 (8 warps).
// Lane mapping: lane = 2*p + r (16 points x 2 bilinear rows per load instr);
// partner partials combine via shfl_xor(1), even lanes store.
// TWO point-groups' loads (16x float4 + 16x predicated scalar) issued in one
// batch before any FMA -> ~32 LDG in flight per thread. (256,2) reg budget.
__global__ void __launch_bounds__(256, 2) fused_kernel(
    const float* __restrict__ image,
    const float* __restrict__ feature,
    const float* __restrict__ pose,
    const float* __restrict__ cam,
    const float* __restrict__ tv,
    const float* __restrict__ fore,
    const float* __restrict__ back,
    float* __restrict__ out)
{
    int n = blockIdx.x, b = blockIdx.y;
    int tid = threadIdx.x;
    LineParams lp = compute_line(pose, cam, tv, b, n);

    const float* fb = feature + (size_t)b * CF * HW * HW;
    float* obase = out + OFF_FEAT + (size_t)b * CF * NL * LL + (size_t)n * LL;

    // ---- setup path (nearest + hist + per-line), l = tid for tid<64 ----
    if (tid < 64) {
        int l = tid;
        float s = __fsub_rn((float)l, 31.5f);
        float x = grid_unnorm(__fadd_rn(lp.cix, __fmul_rn(s, lp.nix)));
        float y = grid_unnorm(__fadd_rn(lp.ciy, __fmul_rn(s, lp.niy)));
        float xr = rintf(x), yr = rintf(y);   // half-to-even = jnp.round
        int xi = (int)xr, yi = (int)yr;
        bool v = (xi >= 0) && (xi < HW) && (yi >= 0) && (yi < HW);

        float i0v = 0.f, i1v = 0.f, i2v = 0.f;
        if (v) {
            const float* ib = image + (size_t)b * 3 * HW * HW + yi * HW + xi;
            i0v = ib[0];
            i1v = ib[HW * HW];
            i2v = ib[2 * HW * HW];
        }
        int b0 = min(max((int)__fmul_rn(i0v, (float)NB), 0), NB - 1);
        int b1 = min(max((int)__fmul_rn(i1v, (float)NB), 0), NB - 1);
        int b2 = min(max((int)__fmul_rn(i2v, (float)NB), 0), NB - 1);
        int hidx = (b0 * NB + b1) * NB + b2;

        float pfv = fore[b * NB * NB * NB + hidx];
        float pbv = back[b * NB * NB * NB + hidx];
        if (pfv < 1e-5f && pbv < 1e-5f) { pfv = 1e-5f; pbv = 1e-5f; }
        float psum = __fadd_rn(pfv, pbv);

        int li = (b * NL + n) * LL + l;
        out[OFF_PF + li] = __fdiv_rn(pfv, psum);
        out[OFF_PB + li] = __fdiv_rn(pbv, psum);

        if (l == 0) {
            int bn = b * NL + n;
            out[OFF_NORM + bn * 2 + 0] = lp.nix;
            out[OFF_NORM + bn * 2 + 1] = lp.niy;
            out[OFF_CIMG + bn * 2 + 0] = lp.cix;
            out[OFF_CIMG + bn * 2 + 1] = lp.ciy;
            out[OFF_CBODY + bn * 3 + 0] = lp.c0;
            out[OFF_CBODY + bn * 3 + 1] = lp.c1;
            out[OFF_CBODY + bn * 3 + 2] = lp.c2;
            out[OFF_VALID + bn] = lp.vline ? 1.f : 0.f;
            out[OFF_AMP + bn]   = 0.43f;
            out[OFF_SLOPE + bn] = 0.5f;
        }
    }

    // ---- feature gathers ----
    int lane = tid & 31;
    int wrp  = tid >> 5;          // 0..7 -> channel group of 8
    int p    = lane >> 1;         // point within group (0..15)
    int r    = lane & 1;          // bilinear row (0 = y0, 1 = y1)

    #pragma unroll
    for (int pp = 0; pp < 2; pp++) {
        int ptA = (pp * 2 + 0) * 16 + p;
        int ptB = (pp * 2 + 1) * 16 + p;
        GDesc dA = make_desc(lp, ptA, r);
        GDesc dB = make_desc(lp, ptB, r);
        bool crA = (dA.ew != 0.f);
        bool crB = (dB.ew != 0.f);

        // ---- one superbatch: both point-groups x 8 channels in flight ----
        float4 qA[8], qB[8];
        float  eA[8], eB[8];
        #pragma unroll
        for (int j = 0; j < 8; j++) {
            int c = wrp * 8 + j;
            const float* fc = fb + (size_t)c * HW * HW;
            qA[j] = __ldg((const float4*)(fc + dA.qoff));
            qB[j] = __ldg((const float4*)(fc + dB.qoff));
            eA[j] = crA ? __ldg(fc + dA.eoff) : 0.f;
            eB[j] = crB ? __ldg(fc + dB.eoff) : 0.f;
        }
        #pragma unroll
        for (int j = 0; j < 8; j++) {
            int c = wrp * 8 + j;
            float sA = qA[j].x * dA.W0 + qA[j].y * dA.W1
                     + qA[j].z * dA.W2 + qA[j].w * dA.W3
                     + eA[j] * dA.ew;
            float fA = sA + __shfl_xor_sync(0xffffffffu, sA, 1);
            if (r == 0) obase[(size_t)c * NL * LL + ptA] = fA;

            float sB = qB[j].x * dB.W0 + qB[j].y * dB.W1
                     + qB[j].z * dB.W2 + qB[j].w * dB.W3
                     + eB[j] * dB.ew;
            float fB = sB + __shfl_xor_sync(0xffffffffu, sB, 1);
            if (r == 0) obase[(size_t)c * NL * LL + ptB] = fB;
        }
    }
}

extern "C" void kernel_launch(void* const* d_in, const int* in_sizes, int n_in,
                              void* d_out, int out_size)
{
    const float* image   = (const float*)d_in[0];
    const float* feature = (const float*)d_in[1];
    const float* pose    = (const float*)d_in[2];
    const float* cam     = (const float*)d_in[3];
    const float* tview   = (const float*)d_in[4];
    const float* fore    = (const float*)d_in[5];
    const float* back    = (const float*)d_in[6];
    float* out = (float*)d_out;

    dim3 grid(NL, BB);
    fused_kernel<<<grid, 256>>>(image, feature, pose, cam, tview,
                                fore, back, out);
}

// round 15
// speedup vs baseline: 1.0801x; 1.0801x over previous
#include <cuda_runtime.h>

#define BB 16
#define NL 200
#define LL 64
#define CF 64
#define HW 256
#define NB 32

// Output layout (float32, flattened in reference-return order)
#define OFF_NORM  0         // (B,N,2)
#define OFF_CIMG  6400      // (B,N,2)
#define OFF_CBODY 12800     // (B,N,3)
#define OFF_PF    22400     // (B,N,64)
#define OFF_PB    227200    // (B,N,64)
#define OFF_VALID 432000    // (B,N)
#define OFF_AMP   435200    // (B,N)
#define OFF_SLOPE 438400    // (B,N)
#define OFF_FEAT  441600    // (B,C,N,64)

struct LineParams {
    float cix, ciy, nix, niy;
    float c0, c1, c2;
    bool  vline;
};

// dot3 with explicit left-to-right rounded adds, no FMA (matches XLA reduce order)
__device__ __forceinline__ float dot3(float a0, float a1, float a2,
                                      float b0, float b1, float b2) {
    return __fadd_rn(__fadd_rn(__fmul_rn(a0, b0), __fmul_rn(a1, b1)),
                     __fmul_rn(a2, b2));
}

__device__ __forceinline__ LineParams compute_line(
    const float* __restrict__ pose,
    const float* __restrict__ cam,
    const float* __restrict__ tv,
    int b, int n)
{
    const float* P = pose + b * 12;
    const float* C = cam + b * 6;
    const float* T = tv + (b * NL + n) * 8;
    float c0 = T[0], c1 = T[1], c2 = T[2];
    float n0 = T[3], n1 = T[4], n2 = T[5];
    float fg = T[6], bg = T[7];

    float civx = __fadd_rn(dot3(c0, c1, c2, P[0], P[1], P[2]), P[9]);
    float civy = __fadd_rn(dot3(c0, c1, c2, P[3], P[4], P[5]), P[10]);
    float civz = __fadd_rn(dot3(c0, c1, c2, P[6], P[7], P[8]), P[11]);
    float nvx  = dot3(n0, n1, n2, P[0], P[1], P[2]);
    float nvy  = dot3(n0, n1, n2, P[3], P[4], P[5]);

    float sw = C[0], sh = C[1], fx = C[2], fy = C[3], cx = C[4], cy = C[5];
    float zz = fmaxf(civz, 1e-4f);
    float cix = __fadd_rn(__fmul_rn(__fdiv_rn(civx, zz), fx), cx);
    float ciy = __fadd_rn(__fmul_rn(__fdiv_rn(civy, zz), fy), cy);

    bool cvalid = (civz > 1e-4f) &&
                  (cix >= 0.f) && (cix <= __fsub_rn(sw, 1.f)) &&
                  (ciy >= 0.f) && (ciy <= __fsub_rn(sh, 1.f));

    float nn  = __fsqrt_rn(__fadd_rn(__fmul_rn(nvx, nvx), __fmul_rn(nvy, nvy)));
    float nd  = fmaxf(nn, 1e-12f);
    float nix = __fdiv_rn(nvx, nd);
    float niy = __fdiv_rn(nvy, nd);

    float cfg = __fdiv_rn(__fmul_rn(fg, fx), civz);
    float cbg = __fdiv_rn(__fmul_rn(bg, fx), civz);
    bool vline = (fminf(cfg, cbg) >= 6.0f) && cvalid;

    float p0x = __fadd_rn(cix, __fmul_rn(-31.5f, nix));
    float p0y = __fadd_rn(ciy, __fmul_rn(-31.5f, niy));
    float p1x = __fadd_rn(cix, __fmul_rn( 31.5f, nix));
    float p1y = __fadd_rn(ciy, __fmul_rn( 31.5f, niy));
    vline = vline &&
        (p0x >= 0.f) && (p0x < (float)HW) && (p0y >= 0.f) && (p0y < (float)HW) &&
        (p1x >= 0.f) && (p1x < (float)HW) && (p1y >= 0.f) && (p1y < (float)HW);

    LineParams lp;
    lp.cix = cix; lp.ciy = ciy; lp.nix = nix; lp.niy = niy;
    lp.c0 = c0; lp.c1 = c1; lp.c2 = c2;
    lp.vline = vline;
    return lp;
}

// Reference grid chain, bit-exact:
//   g = p/size*2 - 1 ;  x = ((g + 1)*size - 1)*0.5
__device__ __forceinline__ float grid_unnorm(float p) {
    float t = __fdiv_rn(p, (float)HW);
    float g = __fsub_rn(__fmul_rn(t, 2.f), 1.f);
    return __fmul_rn(__fsub_rn(__fmul_rn(__fadd_rn(g, 1.f), (float)HW), 1.f), 0.5f);
}

// Fused kernel. grid (NL, BB, 2), block 128 (4 warps).
// blockIdx.z selects the channel half (z*32 + wrp*8 + j). Lane mapping for
// feature gathers: lane = 2*p + r (16 points x 2 bilinear rows per float4
// load). Partner partials combine via shfl_xor(1); even lanes store.
// All 8 channels' loads per point-group issued in ONE batch (MLP~16/thread,
// the measured sweet spot); 128-thr blocks raise resident blocks/SM for
// more issue interleaving at the same per-thread MLP.
__global__ void __launch_bounds__(128, 8) fused_kernel(
    const float* __restrict__ image,
    const float* __restrict__ feature,
    const float* __restrict__ pose,
    const float* __restrict__ cam,
    const float* __restrict__ tv,
    const float* __restrict__ fore,
    const float* __restrict__ back,
    float* __restrict__ out)
{
    int n = blockIdx.x, b = blockIdx.y;
    int zc = blockIdx.z;          // channel half: 0 -> ch 0..31, 1 -> ch 32..63
    int tid = threadIdx.x;
    LineParams lp = compute_line(pose, cam, tv, b, n);

    const float* fb = feature + (size_t)b * CF * HW * HW;
    float* obase = out + OFF_FEAT + (size_t)b * CF * NL * LL + (size_t)n * LL;

    // ---- setup path (nearest + hist + per-line), z==0 blocks, l = tid<64 ----
    if (zc == 0 && tid < 64) {
        int l = tid;
        float s = __fsub_rn((float)l, 31.5f);
        float x = grid_unnorm(__fadd_rn(lp.cix, __fmul_rn(s, lp.nix)));
        float y = grid_unnorm(__fadd_rn(lp.ciy, __fmul_rn(s, lp.niy)));
        float xr = rintf(x), yr = rintf(y);   // half-to-even = jnp.round
        int xi = (int)xr, yi = (int)yr;
        bool v = (xi >= 0) && (xi < HW) && (yi >= 0) && (yi < HW);

        float i0v = 0.f, i1v = 0.f, i2v = 0.f;
        if (v) {
            const float* ib = image + (size_t)b * 3 * HW * HW + yi * HW + xi;
            i0v = ib[0];
            i1v = ib[HW * HW];
            i2v = ib[2 * HW * HW];
        }
        int b0 = min(max((int)__fmul_rn(i0v, (float)NB), 0), NB - 1);
        int b1 = min(max((int)__fmul_rn(i1v, (float)NB), 0), NB - 1);
        int b2 = min(max((int)__fmul_rn(i2v, (float)NB), 0), NB - 1);
        int hidx = (b0 * NB + b1) * NB + b2;

        float pfv = fore[b * NB * NB * NB + hidx];
        float pbv = back[b * NB * NB * NB + hidx];
        if (pfv < 1e-5f && pbv < 1e-5f) { pfv = 1e-5f; pbv = 1e-5f; }
        float psum = __fadd_rn(pfv, pbv);

        int li = (b * NL + n) * LL + l;
        out[OFF_PF + li] = __fdiv_rn(pfv, psum);
        out[OFF_PB + li] = __fdiv_rn(pbv, psum);

        if (l == 0) {
            int bn = b * NL + n;
            out[OFF_NORM + bn * 2 + 0] = lp.nix;
            out[OFF_NORM + bn * 2 + 1] = lp.niy;
            out[OFF_CIMG + bn * 2 + 0] = lp.cix;
            out[OFF_CIMG + bn * 2 + 1] = lp.ciy;
            out[OFF_CBODY + bn * 3 + 0] = lp.c0;
            out[OFF_CBODY + bn * 3 + 1] = lp.c1;
            out[OFF_CBODY + bn * 3 + 2] = lp.c2;
            out[OFF_VALID + bn] = lp.vline ? 1.f : 0.f;
            out[OFF_AMP + bn]   = 0.43f;
            out[OFF_SLOPE + bn] = 0.5f;
        }
    }

    // ---- feature gathers ----
    int lane = tid & 31;
    int wrp  = tid >> 5;          // 0..3
    int cbase = zc * 32 + wrp * 8;
    int p    = lane >> 1;         // point within group (0..15)
    int r    = lane & 1;          // bilinear row (0 = y0, 1 = y1)

    #pragma unroll
    for (int pg = 0; pg < 4; pg++) {
        int pt = pg * 16 + p;
        float s = __fsub_rn((float)pt, 31.5f);
        float x = grid_unnorm(__fadd_rn(lp.cix, __fmul_rn(s, lp.nix)));
        float y = grid_unnorm(__fadd_rn(lp.ciy, __fmul_rn(s, lp.niy)));

        float x0f = floorf(x), y0f = floorf(y);
        float wx1 = __fsub_rn(x, x0f), wy1 = __fsub_rn(y, y0f);
        float wx0 = __fsub_rn(1.f, wx1), wy0 = __fsub_rn(1.f, wy1);
        int x0 = (int)x0f, y0 = (int)y0f;
        int x1 = x0 + 1, y1 = y0 + 1;

        bool vx0 = (x0 >= 0) && (x0 < HW), vx1 = (x1 >= 0) && (x1 < HW);
        bool vy0 = (y0 >= 0) && (y0 < HW), vy1 = (y1 >= 0) && (y1 < HW);
        int xc0 = min(max(x0, 0), HW - 1), xc1 = min(max(x1, 0), HW - 1);
        int yc0 = min(max(y0, 0), HW - 1), yc1 = min(max(y1, 0), HW - 1);

        // this lane's row weights: r==0 -> (w00, w10), r==1 -> (w01, w11)
        float wyr = r ? wy1 : wy0;
        bool  vyr = r ? vy1 : vy0;
        float wl  = (vx0 && vyr) ? __fmul_rn(wx0, wyr) : 0.f;
        float wrt = (vx1 && vyr) ? __fmul_rn(wx1, wyr) : 0.f;
        int   yrr = r ? yc1 : yc0;

        int qx = xc0 & ~3;
        int i0 = xc0 - qx;             // 0..3
        int i1 = i0 + (xc1 - xc0);     // 0..4
        bool cross = (i1 > 3);

        float W[4];
        #pragma unroll
        for (int k = 0; k < 4; k++) {
            float a = (k == i0) ? wl : 0.f;
            if (!cross && k == i1) a += wrt;
            W[k] = a;
        }
        float ew = cross ? wrt : 0.f;
        int qoff = yrr * HW + qx;
        int eoff = yrr * HW + xc1;

        // ---- one batch: all 8 channels' loads in flight before any FMA ----
        float4 q[8];
        float  e[8];
        #pragma unroll
        for (int j = 0; j < 8; j++) {
            int c = cbase + j;
            const float* fc = fb + (size_t)c * HW * HW;
            q[j] = __ldg((const float4*)(fc + qoff));
            e[j] = cross ? __ldg(fc + eoff) : 0.f;
        }
        #pragma unroll
        for (int j = 0; j < 8; j++) {
            int c = cbase + j;
            float sj = q[j].x * W[0] + q[j].y * W[1]
                     + q[j].z * W[2] + q[j].w * W[3]
                     + e[j] * ew;
            float fj = sj + __shfl_xor_sync(0xffffffffu, sj, 1);
            if (r == 0) obase[(size_t)c * NL * LL + pt] = fj;
        }
    }
}

extern "C" void kernel_launch(void* const* d_in, const int* in_sizes, int n_in,
                              void* d_out, int out_size)
{
    const float* image   = (const float*)d_in[0];
    const float* feature = (const float*)d_in[1];
    const float* pose    = (const float*)d_in[2];
    const float* cam     = (const float*)d_in[3];
    const float* tview   = (const float*)d_in[4];
    const float* fore    = (const float*)d_in[5];
    const float* back    = (const float*)d_in[6];
    float* out = (float*)d_out;

    dim3 grid(NL, BB, 2);
    fused_kernel<<<grid, 128>>>(image, feature, pose, cam, tview,
                                fore, back, out);
}

// round 16
// speedup vs baseline: 1.0806x; 1.0004x over previous
#include <cuda_runtime.h>

#define BB 16
#define NL 200
#define LL 64
#define CF 64
#define HW 256
#define NB 32

// Output layout (float32, flattened in reference-return order)
#define OFF_NORM  0         // (B,N,2)
#define OFF_CIMG  6400      // (B,N,2)
#define OFF_CBODY 12800     // (B,N,3)
#define OFF_PF    22400     // (B,N,64)
#define OFF_PB    227200    // (B,N,64)
#define OFF_VALID 432000    // (B,N)
#define OFF_AMP   435200    // (B,N)
#define OFF_SLOPE 438400    // (B,N)
#define OFF_FEAT  441600    // (B,C,N,64)

struct LineParams {
    float cix, ciy, nix, niy;
    float c0, c1, c2;
    bool  vline;
};

// dot3 with explicit left-to-right rounded adds, no FMA (matches XLA reduce order)
__device__ __forceinline__ float dot3(float a0, float a1, float a2,
                                      float b0, float b1, float b2) {
    return __fadd_rn(__fadd_rn(__fmul_rn(a0, b0), __fmul_rn(a1, b1)),
                     __fmul_rn(a2, b2));
}

__device__ __forceinline__ LineParams compute_line(
    const float* __restrict__ pose,
    const float* __restrict__ cam,
    const float* __restrict__ tv,
    int b, int n)
{
    const float* P = pose + b * 12;
    const float* C = cam + b * 6;
    const float* T = tv + (b * NL + n) * 8;
    float c0 = T[0], c1 = T[1], c2 = T[2];
    float n0 = T[3], n1 = T[4], n2 = T[5];
    float fg = T[6], bg = T[7];

    float civx = __fadd_rn(dot3(c0, c1, c2, P[0], P[1], P[2]), P[9]);
    float civy = __fadd_rn(dot3(c0, c1, c2, P[3], P[4], P[5]), P[10]);
    float civz = __fadd_rn(dot3(c0, c1, c2, P[6], P[7], P[8]), P[11]);
    float nvx  = dot3(n0, n1, n2, P[0], P[1], P[2]);
    float nvy  = dot3(n0, n1, n2, P[3], P[4], P[5]);

    float sw = C[0], sh = C[1], fx = C[2], fy = C[3], cx = C[4], cy = C[5];
    float zz = fmaxf(civz, 1e-4f);
    float cix = __fadd_rn(__fmul_rn(__fdiv_rn(civx, zz), fx), cx);
    float ciy = __fadd_rn(__fmul_rn(__fdiv_rn(civy, zz), fy), cy);

    bool cvalid = (civz > 1e-4f) &&
                  (cix >= 0.f) && (cix <= __fsub_rn(sw, 1.f)) &&
                  (ciy >= 0.f) && (ciy <= __fsub_rn(sh, 1.f));

    float nn  = __fsqrt_rn(__fadd_rn(__fmul_rn(nvx, nvx), __fmul_rn(nvy, nvy)));
    float nd  = fmaxf(nn, 1e-12f);
    float nix = __fdiv_rn(nvx, nd);
    float niy = __fdiv_rn(nvy, nd);

    float cfg = __fdiv_rn(__fmul_rn(fg, fx), civz);
    float cbg = __fdiv_rn(__fmul_rn(bg, fx), civz);
    bool vline = (fminf(cfg, cbg) >= 6.0f) && cvalid;

    float p0x = __fadd_rn(cix, __fmul_rn(-31.5f, nix));
    float p0y = __fadd_rn(ciy, __fmul_rn(-31.5f, niy));
    float p1x = __fadd_rn(cix, __fmul_rn( 31.5f, nix));
    float p1y = __fadd_rn(ciy, __fmul_rn( 31.5f, niy));
    vline = vline &&
        (p0x >= 0.f) && (p0x < (float)HW) && (p0y >= 0.f) && (p0y < (float)HW) &&
        (p1x >= 0.f) && (p1x < (float)HW) && (p1y >= 0.f) && (p1y < (float)HW);

    LineParams lp;
    lp.cix = cix; lp.ciy = ciy; lp.nix = nix; lp.niy = niy;
    lp.c0 = c0; lp.c1 = c1; lp.c2 = c2;
    lp.vline = vline;
    return lp;
}

// Reference grid chain, bit-exact:
//   g = p/size*2 - 1 ;  x = ((g + 1)*size - 1)*0.5
// p/256 is a power-of-two division -> EXACT -> identical bits via fmul 2^-8.
__device__ __forceinline__ float grid_unnorm(float p) {
    float t = __fmul_rn(p, 0x1p-8f);                 // == __fdiv_rn(p, 256.f)
    float g = __fsub_rn(__fmul_rn(t, 2.f), 1.f);
    return __fmul_rn(__fsub_rn(__fmul_rn(__fadd_rn(g, 1.f), (float)HW), 1.f), 0.5f);
}

// Fused kernel. grid (NL, BB, 2), block 128 (4 warps).
// blockIdx.z selects the channel half (z*32 + wrp*8 + j). Lane mapping for
// feature gathers: lane = 2*p + r (16 points x 2 bilinear rows per float4
// load). Partner partials combine via shfl_xor(1); even lanes store.
// All 8 channels' loads per point-group issued in ONE batch (MLP~16/thread,
// the measured sweet spot).
__global__ void __launch_bounds__(128, 8) fused_kernel(
    const float* __restrict__ image,
    const float* __restrict__ feature,
    const float* __restrict__ pose,
    const float* __restrict__ cam,
    const float* __restrict__ tv,
    const float* __restrict__ fore,
    const float* __restrict__ back,
    float* __restrict__ out)
{
    int n = blockIdx.x, b = blockIdx.y;
    int zc = blockIdx.z;          // channel half: 0 -> ch 0..31, 1 -> ch 32..63
    int tid = threadIdx.x;
    LineParams lp = compute_line(pose, cam, tv, b, n);

    const float* fb = feature + (size_t)b * CF * HW * HW;
    float* obase = out + OFF_FEAT + (size_t)b * CF * NL * LL + (size_t)n * LL;

    // ---- setup path (nearest + hist + per-line), z==0 blocks, l = tid<64 ----
    if (zc == 0 && tid < 64) {
        int l = tid;
        float s = __fsub_rn((float)l, 31.5f);
        float x = grid_unnorm(__fadd_rn(lp.cix, __fmul_rn(s, lp.nix)));
        float y = grid_unnorm(__fadd_rn(lp.ciy, __fmul_rn(s, lp.niy)));
        float xr = rintf(x), yr = rintf(y);   // half-to-even = jnp.round
        int xi = (int)xr, yi = (int)yr;
        bool v = (xi >= 0) && (xi < HW) && (yi >= 0) && (yi < HW);

        float i0v = 0.f, i1v = 0.f, i2v = 0.f;
        if (v) {
            const float* ib = image + (size_t)b * 3 * HW * HW + yi * HW + xi;
            i0v = ib[0];
            i1v = ib[HW * HW];
            i2v = ib[2 * HW * HW];
        }
        int b0 = min(max((int)__fmul_rn(i0v, (float)NB), 0), NB - 1);
        int b1 = min(max((int)__fmul_rn(i1v, (float)NB), 0), NB - 1);
        int b2 = min(max((int)__fmul_rn(i2v, (float)NB), 0), NB - 1);
        int hidx = (b0 * NB + b1) * NB + b2;

        float pfv = fore[b * NB * NB * NB + hidx];
        float pbv = back[b * NB * NB * NB + hidx];
        if (pfv < 1e-5f && pbv < 1e-5f) { pfv = 1e-5f; pbv = 1e-5f; }
        float psum = __fadd_rn(pfv, pbv);

        int li = (b * NL + n) * LL + l;
        out[OFF_PF + li] = __fdiv_rn(pfv, psum);
        out[OFF_PB + li] = __fdiv_rn(pbv, psum);

        if (l == 0) {
            int bn = b * NL + n;
            out[OFF_NORM + bn * 2 + 0] = lp.nix;
            out[OFF_NORM + bn * 2 + 1] = lp.niy;
            out[OFF_CIMG + bn * 2 + 0] = lp.cix;
            out[OFF_CIMG + bn * 2 + 1] = lp.ciy;
            out[OFF_CBODY + bn * 3 + 0] = lp.c0;
            out[OFF_CBODY + bn * 3 + 1] = lp.c1;
            out[OFF_CBODY + bn * 3 + 2] = lp.c2;
            out[OFF_VALID + bn] = lp.vline ? 1.f : 0.f;
            out[OFF_AMP + bn]   = 0.43f;
            out[OFF_SLOPE + bn] = 0.5f;
        }
    }

    // ---- feature gathers ----
    int lane = tid & 31;
    int wrp  = tid >> 5;          // 0..3
    int cbase = zc * 32 + wrp * 8;
    int p    = lane >> 1;         // point within group (0..15)
    int r    = lane & 1;          // bilinear row (0 = y0, 1 = y1)

    #pragma unroll
    for (int pg = 0; pg < 4; pg++) {
        int pt = pg * 16 + p;
        float s = __fsub_rn((float)pt, 31.5f);
        float x = grid_unnorm(__fadd_rn(lp.cix, __fmul_rn(s, lp.nix)));
        float y = grid_unnorm(__fadd_rn(lp.ciy, __fmul_rn(s, lp.niy)));

        float x0f = floorf(x), y0f = floorf(y);
        float wx1 = __fsub_rn(x, x0f), wy1 = __fsub_rn(y, y0f);
        float wx0 = __fsub_rn(1.f, wx1), wy0 = __fsub_rn(1.f, wy1);
        int x0 = (int)x0f, y0 = (int)y0f;
        int x1 = x0 + 1, y1 = y0 + 1;

        bool vx0 = (x0 >= 0) && (x0 < HW), vx1 = (x1 >= 0) && (x1 < HW);
        bool vy0 = (y0 >= 0) && (y0 < HW), vy1 = (y1 >= 0) && (y1 < HW);
        int xc0 = min(max(x0, 0), HW - 1), xc1 = min(max(x1, 0), HW - 1);
        int yc0 = min(max(y0, 0), HW - 1), yc1 = min(max(y1, 0), HW - 1);

        // this lane's row weights: r==0 -> (w00, w10), r==1 -> (w01, w11)
        float wyr = r ? wy1 : wy0;
        bool  vyr = r ? vy1 : vy0;
        float wl  = (vx0 && vyr) ? __fmul_rn(wx0, wyr) : 0.f;
        float wrt = (vx1 && vyr) ? __fmul_rn(wx1, wyr) : 0.f;
        int   yrr = r ? yc1 : yc0;

        int qx = xc0 & ~3;
        int i0 = xc0 - qx;             // 0..3
        int i1 = i0 + (xc1 - xc0);     // 0..4
        bool cross = (i1 > 3);

        float W[4];
        #pragma unroll
        for (int k = 0; k < 4; k++) {
            float a = (k == i0) ? wl : 0.f;
            if (!cross && k == i1) a += wrt;
            W[k] = a;
        }
        float ew = cross ? wrt : 0.f;
        int qoff = yrr * HW + qx;
        int eoff = yrr * HW + xc1;

        // ---- one batch: all 8 channels' loads in flight before any FMA ----
        float4 q[8];
        float  e[8];
        #pragma unroll
        for (int j = 0; j < 8; j++) {
            int c = cbase + j;
            const float* fc = fb + (size_t)c * HW * HW;
            q[j] = __ldg((const float4*)(fc + qoff));
            e[j] = cross ? __ldg(fc + eoff) : 0.f;
        }
        #pragma unroll
        for (int j = 0; j < 8; j++) {
            int c = cbase + j;
            float sj = q[j].x * W[0] + q[j].y * W[1]
                     + q[j].z * W[2] + q[j].w * W[3]
                     + e[j] * ew;
            float fj = sj + __shfl_xor_sync(0xffffffffu, sj, 1);
            if (r == 0) obase[(size_t)c * NL * LL + pt] = fj;
        }
    }
}

extern "C" void kernel_launch(void* const* d_in, const int* in_sizes, int n_in,
                              void* d_out, int out_size)
{
    const float* image   = (const float*)d_in[0];
    const float* feature = (const float*)d_in[1];
    const float* pose    = (const float*)d_in[2];
    const float* cam     = (const float*)d_in[3];
    const float* tview   = (const float*)d_in[4];
    const float* fore    = (const float*)d_in[5];
    const float* back    = (const float*)d_in[6];
    float* out = (float*)d_out;

    dim3 grid(NL, BB, 2);
    fused_kernel<<<grid, 128>>>(image, feature, pose, cam, tview,
                                fore, back, out);
}